// round 1
// baseline (speedup 1.0000x reference)
#include <cuda_runtime.h>
#include <cstddef>

// Problem constants
#define BATCH 4
#define SEQ   4096
#define DIM   1024
#define QKD   256
#define MTOT  (BATCH*SEQ)   // 16384

// GEMM tiling
#define BM 128
#define BN 128
#define BK 8
#define TM 8
#define TN 8

// Scratch (bss __device__ globals; allocation-free)
__device__ float g_qp[(size_t)BATCH*SEQ*QKD];          //  16.8 MB
__device__ float g_kp[(size_t)BATCH*SEQ*QKD];          //  16.8 MB
__device__ float g_vp[(size_t)BATCH*SEQ*DIM];          //  67.1 MB
__device__ float g_z [(size_t)BATCH*SEQ*SEQ];          // 268.4 MB

// EPI: 0 = +bias[n], 1 = sigmoid(x*scale), 2 = plain
// BKMAJ: true  -> B is [N,K] row-major (C = A * B^T)
//        false -> B is [K,N] row-major (C = A * B)
template<int EPI, bool BKMAJ>
__global__ __launch_bounds__(256, 2)
void gemm_k(const float* __restrict__ A, const float* __restrict__ Bm,
            const float* __restrict__ bias, float* __restrict__ C,
            int M, int N, int K,
            size_t strideA, size_t strideB, size_t strideC,
            float scale)
{
    __shared__ float As[BK][BM];
    __shared__ float Bs[BK][BN];

    const int b = blockIdx.z;
    A  += (size_t)b * strideA;
    Bm += (size_t)b * strideB;
    C  += (size_t)b * strideC;

    const int m0 = blockIdx.y * BM;
    const int n0 = blockIdx.x * BN;
    const int tid = threadIdx.x;
    const int tx = tid & 15;        // 0..15 -> N frag
    const int ty = tid >> 4;        // 0..15 -> M frag

    float acc[TM][TN];
#pragma unroll
    for (int i = 0; i < TM; i++)
#pragma unroll
        for (int j = 0; j < TN; j++) acc[i][j] = 0.f;

    // K-major tile load coords (128 rows x 8 k, one float4 per thread)
    const int arow = tid >> 1;          // 0..127
    const int acol = (tid & 1) * 4;     // 0 or 4
    // N-major (NN) B tile load coords (8 k-rows x 128 n, one float4 per thread)
    const int krow = tid >> 5;          // 0..7
    const int ncol = (tid & 31) * 4;    // 0..124

    for (int k0 = 0; k0 < K; k0 += BK) {
        float4 av = *reinterpret_cast<const float4*>(
            &A[(size_t)(m0 + arow) * K + k0 + acol]);
        As[acol + 0][arow] = av.x;
        As[acol + 1][arow] = av.y;
        As[acol + 2][arow] = av.z;
        As[acol + 3][arow] = av.w;

        if (BKMAJ) {
            float4 bv = *reinterpret_cast<const float4*>(
                &Bm[(size_t)(n0 + arow) * K + k0 + acol]);
            Bs[acol + 0][arow] = bv.x;
            Bs[acol + 1][arow] = bv.y;
            Bs[acol + 2][arow] = bv.z;
            Bs[acol + 3][arow] = bv.w;
        } else {
            float4 bv = *reinterpret_cast<const float4*>(
                &Bm[(size_t)(k0 + krow) * N + n0 + ncol]);
            *reinterpret_cast<float4*>(&Bs[krow][ncol]) = bv;
        }
        __syncthreads();

#pragma unroll
        for (int kk = 0; kk < BK; kk++) {
            float a[TM], bb[TN];
            *reinterpret_cast<float4*>(&a[0]) =
                *reinterpret_cast<const float4*>(&As[kk][ty * TM]);
            *reinterpret_cast<float4*>(&a[4]) =
                *reinterpret_cast<const float4*>(&As[kk][ty * TM + 4]);
            *reinterpret_cast<float4*>(&bb[0]) =
                *reinterpret_cast<const float4*>(&Bs[kk][tx * TN]);
            *reinterpret_cast<float4*>(&bb[4]) =
                *reinterpret_cast<const float4*>(&Bs[kk][tx * TN + 4]);
#pragma unroll
            for (int i = 0; i < TM; i++)
#pragma unroll
                for (int j = 0; j < TN; j++)
                    acc[i][j] += a[i] * bb[j];
        }
        __syncthreads();
    }

    // Epilogue
#pragma unroll
    for (int i = 0; i < TM; i++) {
        const int m = m0 + ty * TM + i;
#pragma unroll
        for (int j = 0; j < TN; j += 4) {
            const int n = n0 + tx * TN + j;
            float4 v;
            v.x = acc[i][j + 0];
            v.y = acc[i][j + 1];
            v.z = acc[i][j + 2];
            v.w = acc[i][j + 3];
            if (EPI == 0) {
                v.x += bias[n + 0];
                v.y += bias[n + 1];
                v.z += bias[n + 2];
                v.w += bias[n + 3];
            } else if (EPI == 1) {
                v.x = 1.f / (1.f + __expf(-v.x * scale));
                v.y = 1.f / (1.f + __expf(-v.y * scale));
                v.z = 1.f / (1.f + __expf(-v.z * scale));
                v.w = 1.f / (1.f + __expf(-v.w * scale));
            }
            *reinterpret_cast<float4*>(&C[(size_t)m * N + n]) = v;
        }
    }
}

extern "C" void kernel_launch(void* const* d_in, const int* in_sizes, int n_in,
                              void* d_out, int out_size)
{
    (void)in_sizes; (void)n_in; (void)out_size;
    const float* q  = (const float*)d_in[0];
    const float* k  = (const float*)d_in[1];
    const float* v  = (const float*)d_in[2];
    const float* Wq = (const float*)d_in[3];
    const float* bq = (const float*)d_in[4];
    const float* Wk = (const float*)d_in[5];
    const float* bk = (const float*)d_in[6];
    const float* Wv = (const float*)d_in[7];
    const float* bv = (const float*)d_in[8];
    float* out = (float*)d_out;

    float *qp, *kp, *vp, *z;
    cudaGetSymbolAddress((void**)&qp, g_qp);
    cudaGetSymbolAddress((void**)&kp, g_kp);
    cudaGetSymbolAddress((void**)&vp, g_vp);
    cudaGetSymbolAddress((void**)&z,  g_z);

    const dim3 blk(256);

    // Projections: C[M,N] = X[M,1024] * W[N,1024]^T + b
    gemm_k<0, true><<<dim3(QKD / BN, MTOT / BM, 1), blk>>>(
        q, Wq, bq, qp, MTOT, QKD, DIM, 0, 0, 0, 0.f);
    gemm_k<0, true><<<dim3(QKD / BN, MTOT / BM, 1), blk>>>(
        k, Wk, bk, kp, MTOT, QKD, DIM, 0, 0, 0, 0.f);
    gemm_k<0, true><<<dim3(DIM / BN, MTOT / BM, 1), blk>>>(
        v, Wv, bv, vp, MTOT, DIM, DIM, 0, 0, 0, 0.f);

    // z[b] = sigmoid( (qp[b] * kp[b]^T) / 16 )   [4096 x 4096 per batch]
    gemm_k<1, true><<<dim3(SEQ / BN, SEQ / BM, BATCH), blk>>>(
        qp, kp, nullptr, z, SEQ, SEQ, QKD,
        (size_t)SEQ * QKD, (size_t)SEQ * QKD, (size_t)SEQ * SEQ, 1.f / 16.f);

    // out[b] = z[b] * vp[b]   [4096 x 1024 per batch], NN layout
    gemm_k<2, false><<<dim3(DIM / BN, SEQ / BM, BATCH), blk>>>(
        z, vp, nullptr, out, SEQ, DIM, SEQ,
        (size_t)SEQ * SEQ, (size_t)SEQ * DIM, (size_t)SEQ * DIM, 0.f);
}

// round 2
// speedup vs baseline: 3.1864x; 3.1864x over previous
#include <cuda_runtime.h>
#include <cstddef>
#include <cstdint>

#define BATCH 4
#define SEQ   4096
#define DIM   1024
#define QKD   256
#define MTOT  (BATCH*SEQ)   // 16384

#define BM 128
#define BN 128
#define BK 32
#define PITCH 40            // floats per smem row (conflict-free frag loads)

// ---------------- scratch (bss device globals; allocation-free) ----------------
__device__ float g_rq [(size_t)MTOT*DIM];   // tf32-rounded inputs
__device__ float g_rk [(size_t)MTOT*DIM];
__device__ float g_rv [(size_t)MTOT*DIM];
__device__ float g_rWq[(size_t)QKD*DIM];
__device__ float g_rWk[(size_t)QKD*DIM];
__device__ float g_rWv[(size_t)DIM*DIM];
__device__ float g_qp [(size_t)MTOT*QKD];
__device__ float g_kp [(size_t)MTOT*QKD];
__device__ float g_vpT[(size_t)DIM*MTOT];   // transposed: [dim][token]
__device__ float g_z  [(size_t)BATCH*SEQ*SEQ];

__device__ __forceinline__ float tf32r(float x) {
    uint32_t u;
    asm("cvt.rna.tf32.f32 %0, %1;" : "=r"(u) : "f"(x));
    return __uint_as_float(u);
}

// elementwise round-to-tf32 pre-pass (float4 vectorized)
__global__ void round_tf32_k(const float* __restrict__ in, float* __restrict__ out, size_t n4) {
    size_t i = (size_t)blockIdx.x * blockDim.x + threadIdx.x;
    size_t stride = (size_t)gridDim.x * blockDim.x;
    for (; i < n4; i += stride) {
        float4 v = reinterpret_cast<const float4*>(in)[i];
        v.x = tf32r(v.x); v.y = tf32r(v.y); v.z = tf32r(v.z); v.w = tf32r(v.w);
        reinterpret_cast<float4*>(out)[i] = v;
    }
}

__device__ __forceinline__ void cpa16(uint32_t smem_dst, const void* gmem_src) {
    asm volatile("cp.async.cg.shared.global [%0], [%1], 16;" :: "r"(smem_dst), "l"(gmem_src));
}

__device__ __forceinline__ void mma_tf32(float* d, const uint32_t* a, const uint32_t* b) {
    asm volatile(
        "mma.sync.aligned.m16n8k8.row.col.f32.tf32.tf32.f32 "
        "{%0,%1,%2,%3}, {%4,%5,%6,%7}, {%8,%9}, {%0,%1,%2,%3};"
        : "+f"(d[0]), "+f"(d[1]), "+f"(d[2]), "+f"(d[3])
        : "r"(a[0]), "r"(a[1]), "r"(a[2]), "r"(a[3]), "r"(b[0]), "r"(b[1]));
}

#define EPI_BIAS   0
#define EPI_SIG    1
#define EPI_NONE   2
#define EPI_BIAS_T 3

// C[m][n] = sum_k A[m][k] * B[n][k]   (both operands K-contiguous)
template<int EPI>
__global__ __launch_bounds__(256, 2)
void mma_gemm(const float* __restrict__ A, const float* __restrict__ B,
              const float* __restrict__ bias, float* __restrict__ C,
              int K, int lda, int ldb, int ldc,
              size_t sA, size_t sB, size_t sC, float scale)
{
    extern __shared__ float sm[];
    float* Asm = sm;                       // 2 * BM * PITCH
    float* Bsm = sm + 2 * BM * PITCH;      // 2 * BN * PITCH

    const int b = blockIdx.z;
    A += (size_t)b * sA;  B += (size_t)b * sB;  C += (size_t)b * sC;

    const int m0 = blockIdx.y * BM;
    const int n0 = blockIdx.x * BN;
    const int tid = threadIdx.x;
    const int lane = tid & 31;
    const int warp = tid >> 5;
    const int wm = warp & 3;       // 4 warps along M  -> warp tile 32 rows
    const int wn = warp >> 2;      // 2 warps along N  -> warp tile 64 cols
    const int r = lane >> 2;       // 0..7
    const int c = lane & 3;        // 0..3

    // staging coords: idx = tid + t*256 -> row = idx>>3 (0..127), f4col = (idx&7)*4
    const int srow = tid >> 1;              // unused pattern placeholder
    (void)srow;

    float acc[2][8][4];
#pragma unroll
    for (int mt = 0; mt < 2; mt++)
#pragma unroll
        for (int nt = 0; nt < 8; nt++)
#pragma unroll
            for (int i = 0; i < 4; i++) acc[mt][nt][i] = 0.f;

    const int nk = K / BK;

    // prologue: stage 0
    {
        const float* Ag = A + (size_t)m0 * lda;
        const float* Bg = B + (size_t)n0 * ldb;
#pragma unroll
        for (int t = 0; t < 4; t++) {
            int idx = tid + t * 256;
            int row = idx >> 3, f4 = (idx & 7) * 4;
            uint32_t da = (uint32_t)__cvta_generic_to_shared(&Asm[row * PITCH + f4]);
            cpa16(da, Ag + (size_t)row * lda + f4);
            uint32_t db = (uint32_t)__cvta_generic_to_shared(&Bsm[row * PITCH + f4]);
            cpa16(db, Bg + (size_t)row * ldb + f4);
        }
        asm volatile("cp.async.commit_group;");
    }

    for (int kt = 0; kt < nk; kt++) {
        const int st = kt & 1;
        if (kt + 1 < nk) {
            const int k0 = (kt + 1) * BK;
            const float* Ag = A + (size_t)m0 * lda + k0;
            const float* Bg = B + (size_t)n0 * ldb + k0;
            float* Ad = Asm + (st ^ 1) * BM * PITCH;
            float* Bd = Bsm + (st ^ 1) * BN * PITCH;
#pragma unroll
            for (int t = 0; t < 4; t++) {
                int idx = tid + t * 256;
                int row = idx >> 3, f4 = (idx & 7) * 4;
                uint32_t da = (uint32_t)__cvta_generic_to_shared(&Ad[row * PITCH + f4]);
                cpa16(da, Ag + (size_t)row * lda + f4);
                uint32_t db = (uint32_t)__cvta_generic_to_shared(&Bd[row * PITCH + f4]);
                cpa16(db, Bg + (size_t)row * ldb + f4);
            }
        }
        asm volatile("cp.async.commit_group;");
        asm volatile("cp.async.wait_group 1;");
        __syncthreads();

        const float* as = Asm + st * BM * PITCH;
        const float* bs = Bsm + st * BN * PITCH;

#pragma unroll
        for (int ks = 0; ks < 4; ks++) {
            uint32_t af[2][4];
#pragma unroll
            for (int mt = 0; mt < 2; mt++) {
                const float* p = as + (wm * 32 + mt * 16 + r) * PITCH + ks * 8 + c;
                af[mt][0] = __float_as_uint(p[0]);
                af[mt][2] = __float_as_uint(p[4]);
                af[mt][1] = __float_as_uint(p[8 * PITCH]);
                af[mt][3] = __float_as_uint(p[8 * PITCH + 4]);
            }
            uint32_t bf[8][2];
#pragma unroll
            for (int nt = 0; nt < 8; nt++) {
                const float* p = bs + (wn * 64 + nt * 8 + r) * PITCH + ks * 8 + c;
                bf[nt][0] = __float_as_uint(p[0]);
                bf[nt][1] = __float_as_uint(p[4]);
            }
#pragma unroll
            for (int mt = 0; mt < 2; mt++)
#pragma unroll
                for (int nt = 0; nt < 8; nt++)
                    mma_tf32(acc[mt][nt], af[mt], bf[nt]);
        }
        __syncthreads();
    }

    // ---------------- epilogue ----------------
#pragma unroll
    for (int mt = 0; mt < 2; mt++) {
#pragma unroll
        for (int nt = 0; nt < 8; nt++) {
            float* d = acc[mt][nt];
            const int m1 = m0 + wm * 32 + mt * 16 + r;
            const int m2 = m1 + 8;
            const int nl = n0 + wn * 64 + nt * 8 + 2 * c;

            if (EPI == EPI_BIAS || EPI == EPI_BIAS_T) {
                const float b0v = bias[nl], b1v = bias[nl + 1];
                d[0] = tf32r(d[0] + b0v);
                d[1] = tf32r(d[1] + b1v);
                d[2] = tf32r(d[2] + b0v);
                d[3] = tf32r(d[3] + b1v);
            } else if (EPI == EPI_SIG) {
                d[0] = tf32r(1.f / (1.f + __expf(-d[0] * scale)));
                d[1] = tf32r(1.f / (1.f + __expf(-d[1] * scale)));
                d[2] = tf32r(1.f / (1.f + __expf(-d[2] * scale)));
                d[3] = tf32r(1.f / (1.f + __expf(-d[3] * scale)));
            }

            if (EPI == EPI_BIAS_T) {
                // C is transposed: C[n][m], leading dim ldc (= MTOT)
                C[(size_t)nl * ldc + m1]       = d[0];
                C[(size_t)(nl + 1) * ldc + m1] = d[1];
                C[(size_t)nl * ldc + m2]       = d[2];
                C[(size_t)(nl + 1) * ldc + m2] = d[3];
            } else {
                float2 v01; v01.x = d[0]; v01.y = d[1];
                float2 v23; v23.x = d[2]; v23.y = d[3];
                *reinterpret_cast<float2*>(&C[(size_t)m1 * ldc + nl]) = v01;
                *reinterpret_cast<float2*>(&C[(size_t)m2 * ldc + nl]) = v23;
            }
        }
    }
}

extern "C" void kernel_launch(void* const* d_in, const int* in_sizes, int n_in,
                              void* d_out, int out_size)
{
    (void)in_sizes; (void)n_in; (void)out_size;
    const float* q  = (const float*)d_in[0];
    const float* k  = (const float*)d_in[1];
    const float* v  = (const float*)d_in[2];
    const float* Wq = (const float*)d_in[3];
    const float* bq = (const float*)d_in[4];
    const float* Wk = (const float*)d_in[5];
    const float* bk = (const float*)d_in[6];
    const float* Wv = (const float*)d_in[7];
    const float* bv = (const float*)d_in[8];
    float* out = (float*)d_out;

    float *rq, *rk, *rv, *rWq, *rWk, *rWv, *qp, *kp, *vpT, *z;
    cudaGetSymbolAddress((void**)&rq,  g_rq);
    cudaGetSymbolAddress((void**)&rk,  g_rk);
    cudaGetSymbolAddress((void**)&rv,  g_rv);
    cudaGetSymbolAddress((void**)&rWq, g_rWq);
    cudaGetSymbolAddress((void**)&rWk, g_rWk);
    cudaGetSymbolAddress((void**)&rWv, g_rWv);
    cudaGetSymbolAddress((void**)&qp,  g_qp);
    cudaGetSymbolAddress((void**)&kp,  g_kp);
    cudaGetSymbolAddress((void**)&vpT, g_vpT);
    cudaGetSymbolAddress((void**)&z,   g_z);

    static bool attr_done = false;
    if (!attr_done) {
        const int smem = 2 * (BM + BN) * PITCH * sizeof(float);  // 81920
        cudaFuncSetAttribute(mma_gemm<EPI_BIAS>,   cudaFuncAttributeMaxDynamicSharedMemorySize, smem);
        cudaFuncSetAttribute(mma_gemm<EPI_BIAS_T>, cudaFuncAttributeMaxDynamicSharedMemorySize, smem);
        cudaFuncSetAttribute(mma_gemm<EPI_SIG>,    cudaFuncAttributeMaxDynamicSharedMemorySize, smem);
        cudaFuncSetAttribute(mma_gemm<EPI_NONE>,   cudaFuncAttributeMaxDynamicSharedMemorySize, smem);
        attr_done = true;
    }
    const int SMEM = 2 * (BM + BN) * PITCH * sizeof(float);
    const dim3 blk(256);

    // tf32 rounding pre-pass
    round_tf32_k<<<1024, 256>>>(q,  rq,  (size_t)MTOT * DIM / 4);
    round_tf32_k<<<1024, 256>>>(k,  rk,  (size_t)MTOT * DIM / 4);
    round_tf32_k<<<1024, 256>>>(v,  rv,  (size_t)MTOT * DIM / 4);
    round_tf32_k<<<256,  256>>>(Wq, rWq, (size_t)QKD * DIM / 4);
    round_tf32_k<<<256,  256>>>(Wk, rWk, (size_t)QKD * DIM / 4);
    round_tf32_k<<<512,  256>>>(Wv, rWv, (size_t)DIM * DIM / 4);

    // qp = q @ Wq^T + bq        [16384, 256]
    mma_gemm<EPI_BIAS><<<dim3(QKD / BN, MTOT / BM, 1), blk, SMEM>>>(
        rq, rWq, bq, qp, DIM, DIM, DIM, QKD, 0, 0, 0, 0.f);
    // kp = k @ Wk^T + bk        [16384, 256]
    mma_gemm<EPI_BIAS><<<dim3(QKD / BN, MTOT / BM, 1), blk, SMEM>>>(
        rk, rWk, bk, kp, DIM, DIM, DIM, QKD, 0, 0, 0, 0.f);
    // vpT = (v @ Wv^T + bv)^T   [1024, 16384]
    mma_gemm<EPI_BIAS_T><<<dim3(DIM / BN, MTOT / BM, 1), blk, SMEM>>>(
        rv, rWv, bv, vpT, DIM, DIM, DIM, MTOT, 0, 0, 0, 0.f);
    // z = sigmoid(qp @ kp^T / 16)   per batch [4096, 4096]
    mma_gemm<EPI_SIG><<<dim3(SEQ / BN, SEQ / BM, BATCH), blk, SMEM>>>(
        qp, kp, nullptr, z, QKD, QKD, QKD, SEQ,
        (size_t)SEQ * QKD, (size_t)SEQ * QKD, (size_t)SEQ * SEQ, 1.f / 16.f);
    // out = z @ vp   per batch [4096, 1024]; B = vpT[n][token], batch offset = b*SEQ along k
    mma_gemm<EPI_NONE><<<dim3(DIM / BN, SEQ / BM, BATCH), blk, SMEM>>>(
        z, vpT, nullptr, out, SEQ, SEQ, MTOT, DIM,
        (size_t)SEQ * SEQ, (size_t)SEQ, (size_t)SEQ * DIM, 0.f);
}

// round 4
// speedup vs baseline: 6.3979x; 2.0078x over previous
#include <cuda_runtime.h>
#include <cuda_fp16.h>
#include <cstddef>
#include <cstdint>

#define BATCH 4
#define SEQ   4096
#define DIM   1024
#define QKD   256
#define MTOT  16384

#define BM 128
#define BN 128
#define BK 32
#define NSTAGE 4
#define PA  40     // A smem pitch (halfs)
#define PB  40     // B TN pitch
#define PBN 136    // B NN pitch
#define ASZ (BM*PA)            // 5120 halfs
#define BSZ (BM*PB)            // 5120 halfs (>= 32*136)
#define STGH (ASZ+BSZ)         // halfs per stage
#define SMEM_DYN (NSTAGE*STGH*2)   // 81920 B

// ---------------- scratch (bss device globals; allocation-free) ----------------
__device__ __half g_hq [(size_t)MTOT*DIM];
__device__ __half g_hk [(size_t)MTOT*DIM];
__device__ __half g_hv [(size_t)MTOT*DIM];
__device__ __half g_hWq[(size_t)QKD*DIM];
__device__ __half g_hWk[(size_t)QKD*DIM];
__device__ __half g_hWv[(size_t)DIM*DIM];
__device__ __half g_qp [(size_t)MTOT*QKD];
__device__ __half g_kp [(size_t)MTOT*QKD];
__device__ __half g_vp [(size_t)MTOT*DIM];
__device__ __half g_z  [(size_t)BATCH*SEQ*SEQ];

// ---------------- helpers ----------------
__device__ __forceinline__ uint32_t s2u(const void* p) {
    return (uint32_t)__cvta_generic_to_shared(p);
}
__device__ __forceinline__ void cpa16(uint32_t dst, const void* src) {
    asm volatile("cp.async.cg.shared.global [%0], [%1], 16;" :: "r"(dst), "l"(src));
}
__device__ __forceinline__ void ldsm4(uint32_t* r, uint32_t a) {
    asm volatile("ldmatrix.sync.aligned.m8n8.x4.shared.b16 {%0,%1,%2,%3}, [%4];"
        : "=r"(r[0]), "=r"(r[1]), "=r"(r[2]), "=r"(r[3]) : "r"(a));
}
__device__ __forceinline__ void ldsm4t(uint32_t* r, uint32_t a) {
    asm volatile("ldmatrix.sync.aligned.m8n8.x4.trans.shared.b16 {%0,%1,%2,%3}, [%4];"
        : "=r"(r[0]), "=r"(r[1]), "=r"(r[2]), "=r"(r[3]) : "r"(a));
}
__device__ __forceinline__ void mma16816(float* d, const uint32_t* a, const uint32_t* b) {
    asm volatile(
        "mma.sync.aligned.m16n8k16.row.col.f32.f16.f16.f32 "
        "{%0,%1,%2,%3}, {%4,%5,%6,%7}, {%8,%9}, {%0,%1,%2,%3};"
        : "+f"(d[0]), "+f"(d[1]), "+f"(d[2]), "+f"(d[3])
        : "r"(a[0]), "r"(a[1]), "r"(a[2]), "r"(a[3]), "r"(b[0]), "r"(b[1]));
}

// ---------------- fused fp32 -> fp16 convert pre-pass ----------------
struct PPArgs {
    const float* src[6];
    __half* dst[6];
    size_t n4[6];
};
__global__ void cvt_half_k(PPArgs pp) {
    const int seg = blockIdx.y;
    const float* in = pp.src[seg];
    __half2* out = reinterpret_cast<__half2*>(pp.dst[seg]);
    const size_t n4 = pp.n4[seg];
    size_t i = (size_t)blockIdx.x * blockDim.x + threadIdx.x;
    const size_t stride = (size_t)gridDim.x * blockDim.x;
    for (; i < n4; i += stride) {
        float4 v = reinterpret_cast<const float4*>(in)[i];
        out[2 * i]     = __floats2half2_rn(v.x, v.y);
        out[2 * i + 1] = __floats2half2_rn(v.z, v.w);
    }
}

// ---------------- fp16 tensor-core GEMM ----------------
// C[m][n] = sum_k A[m][k] * B_frag(n,k)
//   BNN=false: B gmem is [N][K] (K-contig)  -> ldmatrix non-trans
//   BNN=true : B gmem is [K][N] (N-contig)  -> ldmatrix.trans
#define EPI_BIAS 0
#define EPI_SIG  1
#define EPI_NONE 2

template<int EPI, bool BNN, typename OutT>
__global__ __launch_bounds__(256, 2)
void hgemm(const __half* __restrict__ A, const __half* __restrict__ B,
           const float* __restrict__ bias, OutT* __restrict__ C,
           int K, size_t lda, size_t ldb, size_t ldc,
           size_t sA, size_t sB, size_t sC, float scale)
{
    extern __shared__ __align__(128) __half smem[];

    const int b = blockIdx.z;
    A += (size_t)b * sA;  B += (size_t)b * sB;  C += (size_t)b * sC;
    const int m0 = blockIdx.y * BM;
    const int n0 = blockIdx.x * BN;
    const int tid  = threadIdx.x;
    const int lane = tid & 31;
    const int warp = tid >> 5;
    const int wm = warp & 3;     // warp tile: 32 m
    const int wn = warp >> 2;    // warp tile: 64 n
    const uint32_t smem_base = s2u(smem);

    float acc[2][8][4];
#pragma unroll
    for (int mt = 0; mt < 2; mt++)
#pragma unroll
        for (int nt = 0; nt < 8; nt++)
#pragma unroll
            for (int i = 0; i < 4; i++) acc[mt][nt][i] = 0.f;

    const int nk = K / BK;

    auto stage = [&](int kt) {
        const uint32_t so = (uint32_t)(kt & (NSTAGE - 1)) * (STGH * 2);
        const size_t k0 = (size_t)kt * BK;
        // A: 128 rows x 4 chunks(16B) = 512 chunks
#pragma unroll
        for (int i = 0; i < 2; i++) {
            int idx = tid + i * 256;
            int r = idx >> 2, c8 = idx & 3;
            cpa16(smem_base + so + (uint32_t)(r * PA + c8 * 8) * 2,
                  A + (size_t)(m0 + r) * lda + k0 + c8 * 8);
        }
        if (!BNN) {
            // B: 128 rows x 4 chunks
#pragma unroll
            for (int i = 0; i < 2; i++) {
                int idx = tid + i * 256;
                int r = idx >> 2, c8 = idx & 3;
                cpa16(smem_base + so + ASZ * 2 + (uint32_t)(r * PB + c8 * 8) * 2,
                      B + (size_t)(n0 + r) * ldb + k0 + c8 * 8);
            }
        } else {
            // B: 32 k-rows x 16 chunks
#pragma unroll
            for (int i = 0; i < 2; i++) {
                int idx = tid + i * 256;
                int r = idx >> 4, c8 = idx & 15;
                cpa16(smem_base + so + ASZ * 2 + (uint32_t)(r * PBN + c8 * 8) * 2,
                      B + (size_t)(k0 + r) * ldb + n0 + c8 * 8);
            }
        }
    };

    // lane base offsets (bytes)
    const uint32_t aoff  = smem_base + (uint32_t)(((wm * 32 + (lane & 15)) * PA + (lane >> 4) * 8) * 2);
    const uint32_t btoff = smem_base + ASZ * 2 + (uint32_t)(((wn * 64 + (lane & 15)) * PB + (lane >> 4) * 8) * 2);
    const uint32_t bnoff = smem_base + ASZ * 2 + (uint32_t)(((lane & 15) * PBN + wn * 64 + (lane >> 4) * 8) * 2);

    // prologue
#pragma unroll
    for (int kt = 0; kt < NSTAGE - 1; kt++) {
        stage(kt);
        asm volatile("cp.async.commit_group;");
    }

    for (int kt = 0; kt < nk; kt++) {
        asm volatile("cp.async.wait_group %0;" :: "n"(NSTAGE - 2));
        __syncthreads();

        if (kt + NSTAGE - 1 < nk) stage(kt + NSTAGE - 1);
        asm volatile("cp.async.commit_group;");

        const uint32_t so = (uint32_t)(kt & (NSTAGE - 1)) * (STGH * 2);
#pragma unroll
        for (int ks = 0; ks < 2; ks++) {
            uint32_t a[2][4];
            ldsm4(a[0], aoff + so + ks * 32);
            ldsm4(a[1], aoff + so + 16 * PA * 2 + ks * 32);
            uint32_t bf[8][2];
            if (!BNN) {
#pragma unroll
                for (int nt16 = 0; nt16 < 4; nt16++) {
                    uint32_t t[4];
                    ldsm4(t, btoff + so + nt16 * 16 * PB * 2 + ks * 32);
                    bf[2 * nt16][0] = t[0]; bf[2 * nt16][1] = t[2];
                    bf[2 * nt16 + 1][0] = t[1]; bf[2 * nt16 + 1][1] = t[3];
                }
            } else {
#pragma unroll
                for (int nt16 = 0; nt16 < 4; nt16++) {
                    uint32_t t[4];
                    ldsm4t(t, bnoff + so + nt16 * 32 + ks * 16 * PBN * 2);
                    bf[2 * nt16][0] = t[0]; bf[2 * nt16][1] = t[1];
                    bf[2 * nt16 + 1][0] = t[2]; bf[2 * nt16 + 1][1] = t[3];
                }
            }
#pragma unroll
            for (int mt = 0; mt < 2; mt++)
#pragma unroll
                for (int nt = 0; nt < 8; nt++)
                    mma16816(acc[mt][nt], a[mt], bf[nt]);
        }
        __syncthreads();
    }

    // ---------------- epilogue ----------------
    const int r = lane >> 2;
    const int c = lane & 3;
#pragma unroll
    for (int mt = 0; mt < 2; mt++) {
#pragma unroll
        for (int nt = 0; nt < 8; nt++) {
            float* d = acc[mt][nt];
            const int m1 = m0 + wm * 32 + mt * 16 + r;
            const int m2 = m1 + 8;
            const int nl = n0 + wn * 64 + nt * 8 + 2 * c;

            if (EPI == EPI_BIAS) {
                const float b0v = bias[nl], b1v = bias[nl + 1];
                d[0] += b0v; d[1] += b1v; d[2] += b0v; d[3] += b1v;
            } else if (EPI == EPI_SIG) {
                d[0] = 1.f / (1.f + __expf(-d[0] * scale));
                d[1] = 1.f / (1.f + __expf(-d[1] * scale));
                d[2] = 1.f / (1.f + __expf(-d[2] * scale));
                d[3] = 1.f / (1.f + __expf(-d[3] * scale));
            }

            if (sizeof(OutT) == 2) {
                __half2* Ch = reinterpret_cast<__half2*>(const_cast<OutT*>(C));
                Ch[((size_t)m1 * ldc + nl) >> 1] = __floats2half2_rn(d[0], d[1]);
                Ch[((size_t)m2 * ldc + nl) >> 1] = __floats2half2_rn(d[2], d[3]);
            } else {
                float* Cf = reinterpret_cast<float*>(const_cast<OutT*>(C));
                float2 v01; v01.x = d[0]; v01.y = d[1];
                float2 v23; v23.x = d[2]; v23.y = d[3];
                *reinterpret_cast<float2*>(&Cf[(size_t)m1 * ldc + nl]) = v01;
                *reinterpret_cast<float2*>(&Cf[(size_t)m2 * ldc + nl]) = v23;
            }
        }
    }
}

// ---------------- launcher ----------------
extern "C" void kernel_launch(void* const* d_in, const int* in_sizes, int n_in,
                              void* d_out, int out_size)
{
    (void)in_sizes; (void)n_in; (void)out_size;
    const float* q  = (const float*)d_in[0];
    const float* k  = (const float*)d_in[1];
    const float* v  = (const float*)d_in[2];
    const float* Wq = (const float*)d_in[3];
    const float* bq = (const float*)d_in[4];
    const float* Wk = (const float*)d_in[5];
    const float* bk = (const float*)d_in[6];
    const float* Wv = (const float*)d_in[7];
    const float* bv = (const float*)d_in[8];
    float* out = (float*)d_out;

    __half *hq, *hk, *hv, *hWq, *hWk, *hWv, *qp, *kp, *vp, *z;
    cudaGetSymbolAddress((void**)&hq,  g_hq);
    cudaGetSymbolAddress((void**)&hk,  g_hk);
    cudaGetSymbolAddress((void**)&hv,  g_hv);
    cudaGetSymbolAddress((void**)&hWq, g_hWq);
    cudaGetSymbolAddress((void**)&hWk, g_hWk);
    cudaGetSymbolAddress((void**)&hWv, g_hWv);
    cudaGetSymbolAddress((void**)&qp,  g_qp);
    cudaGetSymbolAddress((void**)&kp,  g_kp);
    cudaGetSymbolAddress((void**)&vp,  g_vp);
    cudaGetSymbolAddress((void**)&z,   g_z);

    cudaFuncSetAttribute(hgemm<EPI_BIAS, false, __half>, cudaFuncAttributeMaxDynamicSharedMemorySize, SMEM_DYN);
    cudaFuncSetAttribute(hgemm<EPI_SIG,  false, __half>, cudaFuncAttributeMaxDynamicSharedMemorySize, SMEM_DYN);
    cudaFuncSetAttribute(hgemm<EPI_NONE, true,  float >, cudaFuncAttributeMaxDynamicSharedMemorySize, SMEM_DYN);

    // launch 0: fused fp32->fp16 convert
    PPArgs pp;
    pp.src[0] = q;  pp.dst[0] = hq;  pp.n4[0] = (size_t)MTOT * DIM / 4;
    pp.src[1] = k;  pp.dst[1] = hk;  pp.n4[1] = (size_t)MTOT * DIM / 4;
    pp.src[2] = v;  pp.dst[2] = hv;  pp.n4[2] = (size_t)MTOT * DIM / 4;
    pp.src[3] = Wq; pp.dst[3] = hWq; pp.n4[3] = (size_t)QKD * DIM / 4;
    pp.src[4] = Wk; pp.dst[4] = hWk; pp.n4[4] = (size_t)QKD * DIM / 4;
    pp.src[5] = Wv; pp.dst[5] = hWv; pp.n4[5] = (size_t)DIM * DIM / 4;
    cvt_half_k<<<dim3(512, 6), 256>>>(pp);

    const dim3 blk(256);

    // launch 1: qp = q @ Wq^T + bq   [16384,256] fp16
    hgemm<EPI_BIAS, false, __half><<<dim3(QKD / BN, MTOT / BM, 1), blk, SMEM_DYN>>>(
        hq, hWq, bq, qp, DIM, DIM, DIM, QKD, 0, 0, 0, 0.f);
    // launch 2: kp
    hgemm<EPI_BIAS, false, __half><<<dim3(QKD / BN, MTOT / BM, 1), blk, SMEM_DYN>>>(
        hk, hWk, bk, kp, DIM, DIM, DIM, QKD, 0, 0, 0, 0.f);
    // launch 3: vp = v @ Wv^T + bv   [16384,1024] fp16 (natural layout)
    hgemm<EPI_BIAS, false, __half><<<dim3(DIM / BN, MTOT / BM, 1), blk, SMEM_DYN>>>(
        hv, hWv, bv, vp, DIM, DIM, DIM, DIM, 0, 0, 0, 0.f);
    // launch 4: z = sigmoid(qp @ kp^T / 16)  per batch [4096,4096] fp16
    hgemm<EPI_SIG, false, __half><<<dim3(SEQ / BN, SEQ / BM, BATCH), blk, SMEM_DYN>>>(
        qp, kp, nullptr, z, QKD, QKD, QKD, SEQ,
        (size_t)SEQ * QKD, (size_t)SEQ * QKD, (size_t)SEQ * SEQ, 1.f / 16.f);
    // launch 5: out = z @ vp  per batch [4096,1024] fp32 (NN: vp is [k][n])
    hgemm<EPI_NONE, true, float><<<dim3(DIM / BN, SEQ / BM, BATCH), blk, SMEM_DYN>>>(
        z, vp, nullptr, out, SEQ, SEQ, DIM, DIM,
        (size_t)SEQ * SEQ, (size_t)SEQ * DIM, (size_t)SEQ * DIM, 0.f);
}